// round 1
// baseline (speedup 1.0000x reference)
#include <cuda_runtime.h>
#include <math.h>

// ---------------- problem constants ----------------
#define BB    4
#define CC    64      // DIM
#define HH    256
#define WW    256
#define NPIX  65536   // H*W
#define WH    128     // W/2
#define NSQ   32768   // H*WH
#define NHEAD 4
#define DD    16

// ---------------- scratch (device globals; no allocs allowed) ----------------
__device__ float g_tq[BB * CC * NPIX];   // 64 MB  conv1x1 q (full res)
__device__ float g_tk[BB * CC * NPIX];
__device__ float g_tv[BB * CC * NPIX];
__device__ float g_qs[BB * CC * NSQ];    // 32 MB  squeezed q
__device__ float g_ks[BB * CC * NSQ];    //        squeezed k -> softmaxed in place
__device__ float g_vs[BB * CC * NSQ];
__device__ float g_ctx[BB * NHEAD * DD * DD];
__device__ float g_att[BB * CC * NPIX];  // 64 MB  attention input (pre 5x5)
__device__ float g_m1[BB * 4 * CC * NPIX]; // 256 MB
__device__ float g_m2[BB * 4 * CC * NPIX]; // 256 MB

__device__ __forceinline__ float gelu_f(float x) {
    return 0.5f * x * (1.0f + erff(x * 0.7071067811865476f));
}

// ==================================================================
// K1: fused 1x1 convs for q (nonanchor-masked x1), k (anchor-masked x1), v (x2)
// block = 256 threads: thread -> (px = t&63 within 64-pixel tile, oc chunk = t>>6)
// ==================================================================
__device__ __forceinline__ void loadwT(float* ws, const float* __restrict__ w) {
    for (int i = threadIdx.x; i < 4096; i += 256) {
        int oc = i >> 6, ic = i & 63;
        ws[ic * 68 + oc] = w[i];
    }
}

__device__ __forceinline__ void mm16(const float* __restrict__ ws, const float xr[64],
                                     int chunk, float acc[16]) {
#pragma unroll
    for (int o = 0; o < 16; o++) acc[o] = 0.f;
#pragma unroll
    for (int ic = 0; ic < 64; ic++) {
        float xv = xr[ic];
        const float4* w4 = reinterpret_cast<const float4*>(ws + ic * 68 + chunk * 16);
#pragma unroll
        for (int j = 0; j < 4; j++) {
            float4 w = w4[j];
            acc[j * 4 + 0] += w.x * xv;
            acc[j * 4 + 1] += w.y * xv;
            acc[j * 4 + 2] += w.z * xv;
            acc[j * 4 + 3] += w.w * xv;
        }
    }
}

__global__ void __launch_bounds__(256) k_qkv1x1(
    const float* __restrict__ x1, const float* __restrict__ x2,
    const float* __restrict__ wq, const float* __restrict__ bq,
    const float* __restrict__ wk, const float* __restrict__ bk,
    const float* __restrict__ wv, const float* __restrict__ bv)
{
    __shared__ float ws[64 * 68];
    int t = threadIdx.x;
    int px = t & 63, chunk = t >> 6;
    long base = (long)blockIdx.x * 64;
    int b = (int)(base >> 16);
    int pix = (int)(base & 65535) + px;
    int y = pix >> 8, xc = pix & 255;
    int par = (y + xc) & 1;   // 0 = nonanchor, 1 = anchor

    float xr[64];
    const float* xb = x1 + ((long)b * 64) * 65536 + pix;
#pragma unroll
    for (int ic = 0; ic < 64; ic++) xr[ic] = xb[(long)ic * 65536];

    float acc[16];
    // ---- Q (nonanchor mask) ----
    loadwT(ws, wq);
    __syncthreads();
    mm16(ws, xr, chunk, acc);
#pragma unroll
    for (int o = 0; o < 16; o++) {
        int oc = chunk * 16 + o;
        float bias = bq[oc];
        g_tq[((long)b * 64 + oc) * 65536 + pix] = (par == 0) ? acc[o] + bias : bias;
    }
    __syncthreads();
    // ---- K (anchor mask) ----
    loadwT(ws, wk);
    __syncthreads();
    mm16(ws, xr, chunk, acc);
#pragma unroll
    for (int o = 0; o < 16; o++) {
        int oc = chunk * 16 + o;
        float bias = bk[oc];
        g_tk[((long)b * 64 + oc) * 65536 + pix] = (par == 1) ? acc[o] + bias : bias;
    }
    __syncthreads();
    // ---- V (no mask, input x2) ----
    loadwT(ws, wv);
    __syncthreads();
    const float* xb2 = x2 + ((long)b * 64) * 65536 + pix;
#pragma unroll
    for (int ic = 0; ic < 64; ic++) xr[ic] = xb2[(long)ic * 65536];
    mm16(ws, xr, chunk, acc);
#pragma unroll
    for (int o = 0; o < 16; o++) {
        int oc = chunk * 16 + o;
        g_tv[((long)b * 64 + oc) * 65536 + pix] = acc[o] + bv[oc];
    }
}

// ==================================================================
// K2: depthwise 3x3 (pad 1) + parity squeeze.
// grid = (H, B*C, 3{q,k,v}), block = 128 (one squeezed row)
// q: j = 2c' + (r&1)  (nonanchor) ; k,v: j = 2c' + 1-(r&1) (anchor)
// ==================================================================
__global__ void __launch_bounds__(128) k_dw_squeeze(
    const float* __restrict__ q2w, const float* __restrict__ q2b,
    const float* __restrict__ k2w, const float* __restrict__ k2b,
    const float* __restrict__ v2w, const float* __restrict__ v2b)
{
    int r = blockIdx.x;
    int bc = blockIdx.y;           // b*64 + c
    int c = bc & 63;
    int which = blockIdx.z;
    const float* src; const float* wz; const float* bz; float* dst; int joff;
    if (which == 0)      { src = g_tq; wz = q2w; bz = q2b; dst = g_qs; joff = r & 1; }
    else if (which == 1) { src = g_tk; wz = k2w; bz = k2b; dst = g_ks; joff = 1 - (r & 1); }
    else                 { src = g_tv; wz = v2w; bz = v2b; dst = g_vs; joff = 1 - (r & 1); }

    __shared__ float srow[3][258];
    const float* base = src + (long)bc * 65536;
    for (int i = threadIdx.x; i < 3 * 258; i += 128) {
        int row = i / 258, xx = i % 258;
        int yy = r - 1 + row, x = xx - 1;
        srow[row][xx] = (yy >= 0 && yy < 256 && x >= 0 && x < 256) ? base[yy * 256 + x] : 0.f;
    }
    __syncthreads();

    float w[9];
#pragma unroll
    for (int i = 0; i < 9; i++) w[i] = wz[c * 9 + i];

    int cp = threadIdx.x;
    int j = 2 * cp + joff;
    float acc = bz[c];
#pragma unroll
    for (int ky = 0; ky < 3; ky++)
#pragma unroll
        for (int kx = 0; kx < 3; kx++)
            acc += srow[ky][j + kx] * w[ky * 3 + kx];
    dst[(long)bc * 32768 + r * 128 + cp] = acc;
}

// ==================================================================
// K3: softmax of k over spatial (per b,c row of 32768), in place
// ==================================================================
__global__ void __launch_bounds__(256) k_ksoftmax()
{
    int bc = blockIdx.x;
    float* row = g_ks + (long)bc * 32768;
    __shared__ float red[256];
    int t = threadIdx.x;
    float m = -1e30f;
    for (int i = t; i < 32768; i += 256) m = fmaxf(m, row[i]);
    red[t] = m; __syncthreads();
    for (int s = 128; s > 0; s >>= 1) { if (t < s) red[t] = fmaxf(red[t], red[t + s]); __syncthreads(); }
    m = red[0]; __syncthreads();
    float sum = 0.f;
    for (int i = t; i < 32768; i += 256) sum += __expf(row[i] - m);
    red[t] = sum; __syncthreads();
    for (int s = 128; s > 0; s >>= 1) { if (t < s) red[t] += red[t + s]; __syncthreads(); }
    float inv = 1.0f / red[0];
    for (int i = t; i < 32768; i += 256) row[i] = __expf(row[i] - m) * inv;
}

// ==================================================================
// K4: ctx[b,h,d,e] = sum_n ksm[d,n] * v[e,n]   (chunked, atomic reduce)
// ==================================================================
__global__ void __launch_bounds__(256) k_zero_ctx()
{
    int i = blockIdx.x * 256 + threadIdx.x;
    if (i < BB * NHEAD * DD * DD) g_ctx[i] = 0.f;
}

__global__ void __launch_bounds__(256) k_ctx()
{
    __shared__ float sk[16][257];
    __shared__ float sv[16][257];
    int bh = blockIdx.x;                  // b*4 + h
    int ch = blockIdx.y;                  // n-chunk (256 each)
    int b = bh >> 2, h = bh & 3;
    long rowbase = ((long)b * 64 + h * 16) * 32768 + ch * 256;
    int t = threadIdx.x;
    for (int i = t; i < 16 * 256; i += 256) {
        int d = i >> 8, n = i & 255;
        sk[d][n] = g_ks[rowbase + (long)d * 32768 + n];
        sv[d][n] = g_vs[rowbase + (long)d * 32768 + n];
    }
    __syncthreads();
    int d = t >> 4, e = t & 15;
    float a = 0.f;
#pragma unroll 8
    for (int n = 0; n < 256; n++) a += sk[d][n] * sv[e][n];
    atomicAdd(&g_ctx[(bh << 8) + (d << 4) + e], a);
}

// ==================================================================
// K5: per squeezed position: softmax(q over d) then att = ctx^T q,
//     scatter to full res (zeros at anchor parity). grid=(H, B), block=128 (c')
// ==================================================================
__global__ void __launch_bounds__(128) k_att()
{
    int r = blockIdx.x, b = blockIdx.y;
    __shared__ float cs[NHEAD * DD * DD];   // ctx for this b
    int t = threadIdx.x;
    for (int i = t; i < NHEAD * DD * DD; i += 128) cs[i] = g_ctx[b * (NHEAD * DD * DD) + i];
    __syncthreads();

    int cp = t;
    float qv[64];
    const float* qbase = g_qs + (long)b * 64 * 32768 + r * 128 + cp;
#pragma unroll
    for (int c = 0; c < 64; c++) qv[c] = qbase[(long)c * 32768];

    int odd = r & 1;
    float2* out = (float2*)(g_att + ((long)b * 64) * 65536 + (long)r * 256) + cp;

#pragma unroll
    for (int h = 0; h < 4; h++) {
        float m = -1e30f;
#pragma unroll
        for (int d = 0; d < 16; d++) m = fmaxf(m, qv[h * 16 + d]);
        float s = 0.f;
#pragma unroll
        for (int d = 0; d < 16; d++) { float e = __expf(qv[h * 16 + d] - m); qv[h * 16 + d] = e; s += e; }
        float inv = 1.0f / s;
#pragma unroll
        for (int e = 0; e < 16; e++) {
            float a = 0.f;
#pragma unroll
            for (int d = 0; d < 16; d++) a += cs[h * 256 + d * 16 + e] * qv[h * 16 + d];
            a *= inv;
            int c = h * 16 + e;
            float2 v = odd ? make_float2(0.f, a) : make_float2(a, 0.f);
            out[(long)c * 32768] = v;
        }
    }
}

// ==================================================================
// K6: conv5x5 (64 -> 128, pad 2) -> d_out ("attention")
// grid = (W/32, H/8, B*4), block 256: thread = pixel in 8x32 tile, 32 oc per block
// ==================================================================
__global__ void __launch_bounds__(256) k_conv5x5(
    const float* __restrict__ rw, const float* __restrict__ rb, float* __restrict__ out)
{
    __shared__ float s_in[12 * 36];
    __shared__ float s_w[32 * 28];
    int bz = blockIdx.z;
    int b = bz >> 2, ocg = bz & 3;
    int y0 = blockIdx.y * 8, x0 = blockIdx.x * 32;
    int t = threadIdx.x;
    int py = t >> 5, px = t & 31;
    float acc[32];
#pragma unroll
    for (int o = 0; o < 32; o++) acc[o] = 0.f;

    const float* inb = g_att + (long)b * 64 * 65536;
    int ocbase = ocg * 32;

    for (int ic = 0; ic < 64; ic++) {
        for (int i = t; i < 432; i += 256) {
            int iy = i / 36, ix = i % 36;
            int gy = y0 - 2 + iy, gx = x0 - 2 + ix;
            s_in[i] = (gy >= 0 && gy < 256 && gx >= 0 && gx < 256)
                      ? inb[(long)ic * 65536 + gy * 256 + gx] : 0.f;
        }
        for (int i = t; i < 32 * 28; i += 256) {
            int o = i / 28, k = i % 28;
            s_w[i] = (k < 25) ? rw[((long)(ocbase + o) * 64 + ic) * 25 + k] : 0.f;
        }
        __syncthreads();

        float win[28];
#pragma unroll
        for (int k = 0; k < 28; k++) win[k] = 0.f;
#pragma unroll
        for (int ky = 0; ky < 5; ky++)
#pragma unroll
            for (int kx = 0; kx < 5; kx++)
                win[ky * 5 + kx] = s_in[(py + ky) * 36 + px + kx];

#pragma unroll
        for (int o = 0; o < 32; o++) {
            const float4* wv = (const float4*)(s_w + o * 28);
            float a = acc[o];
#pragma unroll
            for (int k4 = 0; k4 < 7; k4++) {
                float4 w4 = wv[k4];
                a += w4.x * win[k4 * 4 + 0] + w4.y * win[k4 * 4 + 1]
                   + w4.z * win[k4 * 4 + 2] + w4.w * win[k4 * 4 + 3];
            }
            acc[o] = a;
        }
        __syncthreads();
    }

    long obase = ((long)b * 128 + ocbase) * 65536 + (long)(y0 + py) * 256 + x0 + px;
#pragma unroll
    for (int o = 0; o < 32; o++)
        out[obase + (long)o * 65536] = acc[o] + rb[ocbase + o];
}

// ==================================================================
// K7: m1 = gelu(conv1x1 128->256). block 256 (thread = oc), 32-pixel tile.
// ==================================================================
__global__ void __launch_bounds__(256) k_m1(
    const float* __restrict__ att, const float* __restrict__ w, const float* __restrict__ bias)
{
    __shared__ float sbuf[8192];    // phase A: [32 px][stride 132] input ; phase B: [256 oc][32 px]
    int t = threadIdx.x;
    long pix0 = (long)blockIdx.x * 32;
    int b = (int)(pix0 >> 16);
    int pp = (int)(pix0 & 65535);
    const float* ab = att + ((long)b * 128) * 65536 + pp;
    for (int i = t; i < 4096; i += 256) {
        int ic = i >> 5, p = i & 31;
        sbuf[p * 132 + ic] = ab[(long)ic * 65536 + p];
    }
    __syncthreads();

    int oc = t;
    float acc[32];
#pragma unroll
    for (int p = 0; p < 32; p++) acc[p] = bias[oc];
    const float* wr = w + oc * 128;
#pragma unroll
    for (int chunk = 0; chunk < 2; chunk++) {
        float wl[64];
#pragma unroll
        for (int i = 0; i < 16; i++) {
            float4 w4 = *(const float4*)(wr + chunk * 64 + i * 4);
            wl[i * 4] = w4.x; wl[i * 4 + 1] = w4.y; wl[i * 4 + 2] = w4.z; wl[i * 4 + 3] = w4.w;
        }
#pragma unroll
        for (int p = 0; p < 32; p++) {
            const float4* xs = (const float4*)(sbuf + p * 132 + chunk * 64);
            float a = acc[p];
#pragma unroll
            for (int i = 0; i < 16; i++) {
                float4 x4 = xs[i];
                a += wl[i * 4] * x4.x + wl[i * 4 + 1] * x4.y + wl[i * 4 + 2] * x4.z + wl[i * 4 + 3] * x4.w;
            }
            acc[p] = a;
        }
    }
    __syncthreads();
#pragma unroll
    for (int p = 0; p < 32; p++) sbuf[oc * 32 + p] = gelu_f(acc[p]);
    __syncthreads();
    float* ob = g_m1 + ((long)b * 256) * 65536 + pp;
    for (int i = t; i < 8192; i += 256) {
        int o = i >> 5, p = i & 31;
        ob[(long)o * 65536 + p] = sbuf[i];
    }
}

// ==================================================================
// K8: m2 = gelu(depthwise 3x3 over 256 ch). grid (H, B*256), block 256.
// ==================================================================
__global__ void __launch_bounds__(256) k_m2(
    const float* __restrict__ w, const float* __restrict__ bias)
{
    int r = blockIdx.x;
    int bc = blockIdx.y;            // b*256 + c
    int c = bc & 255;
    const float* base = g_m1 + (long)bc * 65536;
    __shared__ float srow[3][258];
    for (int i = threadIdx.x; i < 3 * 258; i += 256) {
        int row = i / 258, xx = i % 258;
        int yy = r - 1 + row, x = xx - 1;
        srow[row][xx] = (yy >= 0 && yy < 256 && x >= 0 && x < 256) ? base[yy * 256 + x] : 0.f;
    }
    __syncthreads();
    float wl[9];
#pragma unroll
    for (int i = 0; i < 9; i++) wl[i] = w[c * 9 + i];
    int x = threadIdx.x;
    float acc = bias[c];
#pragma unroll
    for (int ky = 0; ky < 3; ky++)
#pragma unroll
        for (int kx = 0; kx < 3; kx++)
            acc += srow[ky][x + kx] * wl[ky * 3 + kx];
    g_m2[(long)bc * 65536 + (long)r * 256 + x] = gelu_f(acc);
}

// ==================================================================
// K9: out = attention(d_out) + conv1x1(m2, 256->128) + b. block 128 (thread=oc).
// ==================================================================
__global__ void __launch_bounds__(128) k_m3(
    float* __restrict__ out, const float* __restrict__ w, const float* __restrict__ bias)
{
    __shared__ float sbuf[8320];   // phase A: [32 px][stride 260]; phase B: [128 oc][32 px]
    int t = threadIdx.x;
    long pix0 = (long)blockIdx.x * 32;
    int b = (int)(pix0 >> 16);
    int pp = (int)(pix0 & 65535);
    const float* ib = g_m2 + ((long)b * 256) * 65536 + pp;
    for (int i = t; i < 8192; i += 128) {
        int ic = i >> 5, p = i & 31;
        sbuf[p * 260 + ic] = ib[(long)ic * 65536 + p];
    }
    __syncthreads();

    int oc = t;
    float acc[32];
#pragma unroll
    for (int p = 0; p < 32; p++) acc[p] = bias[oc];
    const float* wr = w + oc * 256;
#pragma unroll
    for (int chunk = 0; chunk < 4; chunk++) {
        float wl[64];
#pragma unroll
        for (int i = 0; i < 16; i++) {
            float4 w4 = *(const float4*)(wr + chunk * 64 + i * 4);
            wl[i * 4] = w4.x; wl[i * 4 + 1] = w4.y; wl[i * 4 + 2] = w4.z; wl[i * 4 + 3] = w4.w;
        }
#pragma unroll
        for (int p = 0; p < 32; p++) {
            const float4* xs = (const float4*)(sbuf + p * 260 + chunk * 64);
            float a = acc[p];
#pragma unroll
            for (int i = 0; i < 16; i++) {
                float4 x4 = xs[i];
                a += wl[i * 4] * x4.x + wl[i * 4 + 1] * x4.y + wl[i * 4 + 2] * x4.z + wl[i * 4 + 3] * x4.w;
            }
            acc[p] = a;
        }
    }
    __syncthreads();
#pragma unroll
    for (int p = 0; p < 32; p++) sbuf[oc * 32 + p] = acc[p];
    __syncthreads();
    float* ob = out + ((long)b * 128) * 65536 + pp;
    for (int i = t; i < 4096; i += 128) {
        int o = i >> 5, p = i & 31;
        long a = (long)o * 65536 + p;
        ob[a] = ob[a] + sbuf[i];
    }
}

// ==================================================================
extern "C" void kernel_launch(void* const* d_in, const int* in_sizes, int n_in,
                              void* d_out, int out_size)
{
    const float* x1  = (const float*)d_in[0];
    const float* x2  = (const float*)d_in[1];
    const float* q1w = (const float*)d_in[2];  const float* q1b = (const float*)d_in[3];
    const float* q2w = (const float*)d_in[4];  const float* q2b = (const float*)d_in[5];
    const float* k1w = (const float*)d_in[6];  const float* k1b = (const float*)d_in[7];
    const float* k2w = (const float*)d_in[8];  const float* k2b = (const float*)d_in[9];
    const float* v1w = (const float*)d_in[10]; const float* v1b = (const float*)d_in[11];
    const float* v2w = (const float*)d_in[12]; const float* v2b = (const float*)d_in[13];
    const float* rw  = (const float*)d_in[14]; const float* rb  = (const float*)d_in[15];
    const float* m1w = (const float*)d_in[16]; const float* m1b = (const float*)d_in[17];
    const float* m2w = (const float*)d_in[18]; const float* m2b = (const float*)d_in[19];
    const float* m3w = (const float*)d_in[20]; const float* m3b = (const float*)d_in[21];
    float* out = (float*)d_out;

    k_qkv1x1<<<4096, 256>>>(x1, x2, q1w, q1b, k1w, k1b, v1w, v1b);
    k_dw_squeeze<<<dim3(256, 256, 3), 128>>>(q2w, q2b, k2w, k2b, v2w, v2b);
    k_ksoftmax<<<256, 256>>>();
    k_zero_ctx<<<16, 256>>>();
    k_ctx<<<dim3(16, 128), 256>>>();
    k_att<<<dim3(256, 4), 128>>>();
    k_conv5x5<<<dim3(8, 32, 16), 256>>>(rw, rb, out);
    k_m1<<<8192, 256>>>(out, m1w, m1b);
    k_m2<<<dim3(256, 1024), 256>>>(m2w, m2b);
    k_m3<<<8192, 128>>>(out, m3w, m3b);
}

// round 2
// speedup vs baseline: 1.1516x; 1.1516x over previous
#include <cuda_runtime.h>
#include <math.h>

typedef unsigned long long ull;

// ---------------- problem constants ----------------
#define BB    4
#define CC    64
#define HH    256
#define WW    256
#define NPIX  65536
#define NSQ   32768
#define NHEAD 4
#define DD    16

// ---------------- scratch ----------------
__device__ float g_tq[BB * CC * NPIX];
__device__ float g_tk[BB * CC * NPIX];
__device__ float g_tv[BB * CC * NPIX];
__device__ float g_qs[BB * CC * NSQ];
__device__ float g_ks[BB * CC * NSQ];
__device__ float g_vs[BB * CC * NSQ];
__device__ float g_ctx[BB * NHEAD * DD * DD];
__device__ float g_att[BB * CC * NPIX];
__device__ float g_m1[BB * 4 * CC * NPIX];
__device__ float g_m2[BB * 4 * CC * NPIX];
// prepacked weights
__device__ __align__(16) float g_w1T[128 * 256];          // m1 weights transposed [ic][oc]
__device__ __align__(16) float g_w3T[256 * 128];          // m3 weights transposed [ic][oc]
__device__ __align__(16) ull   g_rw2[64 * 128 * 30];      // conv5x5 weights, duplicated pairs, ky-stride 6

// ---------------- f32x2 helpers ----------------
__device__ __forceinline__ ull pk2(float lo, float hi) {
    ull r; asm("mov.b64 %0,{%1,%2};" : "=l"(r) : "f"(lo), "f"(hi)); return r;
}
__device__ __forceinline__ void upk2(float& lo, float& hi, ull v) {
    asm("mov.b64 {%0,%1},%2;" : "=f"(lo), "=f"(hi) : "l"(v));
}
__device__ __forceinline__ void fma2(ull& d, ull a, ull b) {
    asm("fma.rn.f32x2 %0,%1,%2,%0;" : "+l"(d) : "l"(a), "l"(b));
}
__device__ __forceinline__ float gelu_f(float x) {
    return 0.5f * x * (1.0f + erff(x * 0.7071067811865476f));
}

// ==================================================================
// K0: prepack weights (transpose m1/m3, duplicate conv5x5 pairs)
// ==================================================================
__global__ void __launch_bounds__(256) k_prep(
    const float* __restrict__ m1w, const float* __restrict__ m3w, const float* __restrict__ rw)
{
    int i = blockIdx.x * 256 + threadIdx.x;
    if (i < 32768) {
        { int oc = i >> 7, ic = i & 127; g_w1T[ic * 256 + oc] = m1w[i]; }   // m1w[oc*128+ic]
        { int oc = i >> 8, ic = i & 255; g_w3T[ic * 128 + oc] = m3w[i]; }   // m3w[oc*256+ic]
    }
    if (i < 204800) {   // rw[(oc*64+ic)*25 + k]
        int k = i % 25; int rest = i / 25;
        int ic = rest & 63, oc = rest >> 6;
        int ky = k / 5, kx = k - ky * 5;
        float v = rw[i];
        g_rw2[((long)ic * 128 + oc) * 30 + ky * 6 + kx] = pk2(v, v);
    }
}

// ==================================================================
// K1: fused 1x1 convs for q/k/v (masked)
// ==================================================================
__device__ __forceinline__ void loadwT(float* ws, const float* __restrict__ w) {
    for (int i = threadIdx.x; i < 4096; i += 256) {
        int oc = i >> 6, ic = i & 63;
        ws[ic * 68 + oc] = w[i];
    }
}
__device__ __forceinline__ void mm16(const float* __restrict__ ws, const float xr[64],
                                     int chunk, float acc[16]) {
#pragma unroll
    for (int o = 0; o < 16; o++) acc[o] = 0.f;
#pragma unroll
    for (int ic = 0; ic < 64; ic++) {
        float xv = xr[ic];
        const float4* w4 = reinterpret_cast<const float4*>(ws + ic * 68 + chunk * 16);
#pragma unroll
        for (int j = 0; j < 4; j++) {
            float4 w = w4[j];
            acc[j * 4 + 0] += w.x * xv;
            acc[j * 4 + 1] += w.y * xv;
            acc[j * 4 + 2] += w.z * xv;
            acc[j * 4 + 3] += w.w * xv;
        }
    }
}
__global__ void __launch_bounds__(256) k_qkv1x1(
    const float* __restrict__ x1, const float* __restrict__ x2,
    const float* __restrict__ wq, const float* __restrict__ bq,
    const float* __restrict__ wk, const float* __restrict__ bk,
    const float* __restrict__ wv, const float* __restrict__ bv)
{
    __shared__ float ws[64 * 68];
    int t = threadIdx.x;
    int px = t & 63, chunk = t >> 6;
    long base = (long)blockIdx.x * 64;
    int b = (int)(base >> 16);
    int pix = (int)(base & 65535) + px;
    int y = pix >> 8, xc = pix & 255;
    int par = (y + xc) & 1;

    float xr[64];
    const float* xb = x1 + ((long)b * 64) * 65536 + pix;
#pragma unroll
    for (int ic = 0; ic < 64; ic++) xr[ic] = xb[(long)ic * 65536];

    float acc[16];
    loadwT(ws, wq); __syncthreads();
    mm16(ws, xr, chunk, acc);
#pragma unroll
    for (int o = 0; o < 16; o++) {
        int oc = chunk * 16 + o; float bias = bq[oc];
        g_tq[((long)b * 64 + oc) * 65536 + pix] = (par == 0) ? acc[o] + bias : bias;
    }
    __syncthreads();
    loadwT(ws, wk); __syncthreads();
    mm16(ws, xr, chunk, acc);
#pragma unroll
    for (int o = 0; o < 16; o++) {
        int oc = chunk * 16 + o; float bias = bk[oc];
        g_tk[((long)b * 64 + oc) * 65536 + pix] = (par == 1) ? acc[o] + bias : bias;
    }
    __syncthreads();
    loadwT(ws, wv); __syncthreads();
    const float* xb2 = x2 + ((long)b * 64) * 65536 + pix;
#pragma unroll
    for (int ic = 0; ic < 64; ic++) xr[ic] = xb2[(long)ic * 65536];
    mm16(ws, xr, chunk, acc);
#pragma unroll
    for (int o = 0; o < 16; o++) {
        int oc = chunk * 16 + o;
        g_tv[((long)b * 64 + oc) * 65536 + pix] = acc[o] + bv[oc];
    }
}

// ==================================================================
// K2: depthwise 3x3 + parity squeeze
// ==================================================================
__global__ void __launch_bounds__(128) k_dw_squeeze(
    const float* __restrict__ q2w, const float* __restrict__ q2b,
    const float* __restrict__ k2w, const float* __restrict__ k2b,
    const float* __restrict__ v2w, const float* __restrict__ v2b)
{
    int r = blockIdx.x;
    int bc = blockIdx.y;
    int c = bc & 63;
    int which = blockIdx.z;
    const float* src; const float* wz; const float* bz; float* dst; int joff;
    if (which == 0)      { src = g_tq; wz = q2w; bz = q2b; dst = g_qs; joff = r & 1; }
    else if (which == 1) { src = g_tk; wz = k2w; bz = k2b; dst = g_ks; joff = 1 - (r & 1); }
    else                 { src = g_tv; wz = v2w; bz = v2b; dst = g_vs; joff = 1 - (r & 1); }

    __shared__ float srow[3][258];
    const float* base = src + (long)bc * 65536;
    for (int i = threadIdx.x; i < 3 * 258; i += 128) {
        int row = i / 258, xx = i % 258;
        int yy = r - 1 + row, x = xx - 1;
        srow[row][xx] = (yy >= 0 && yy < 256 && x >= 0 && x < 256) ? base[yy * 256 + x] : 0.f;
    }
    __syncthreads();
    float w[9];
#pragma unroll
    for (int i = 0; i < 9; i++) w[i] = wz[c * 9 + i];
    int cp = threadIdx.x;
    int j = 2 * cp + joff;
    float acc = bz[c];
#pragma unroll
    for (int ky = 0; ky < 3; ky++)
#pragma unroll
        for (int kx = 0; kx < 3; kx++)
            acc += srow[ky][j + kx] * w[ky * 3 + kx];
    dst[(long)bc * 32768 + r * 128 + cp] = acc;
}

// ==================================================================
// K3: k softmax over spatial
// ==================================================================
__global__ void __launch_bounds__(256) k_ksoftmax()
{
    int bc = blockIdx.x;
    float* row = g_ks + (long)bc * 32768;
    __shared__ float red[256];
    int t = threadIdx.x;
    float m = -1e30f;
    for (int i = t; i < 32768; i += 256) m = fmaxf(m, row[i]);
    red[t] = m; __syncthreads();
    for (int s = 128; s > 0; s >>= 1) { if (t < s) red[t] = fmaxf(red[t], red[t + s]); __syncthreads(); }
    m = red[0]; __syncthreads();
    float sum = 0.f;
    for (int i = t; i < 32768; i += 256) sum += __expf(row[i] - m);
    red[t] = sum; __syncthreads();
    for (int s = 128; s > 0; s >>= 1) { if (t < s) red[t] += red[t + s]; __syncthreads(); }
    float inv = 1.0f / red[0];
    for (int i = t; i < 32768; i += 256) row[i] = __expf(row[i] - m) * inv;
}

// ==================================================================
// K4: ctx
// ==================================================================
__global__ void __launch_bounds__(256) k_zero_ctx()
{
    int i = blockIdx.x * 256 + threadIdx.x;
    if (i < BB * NHEAD * DD * DD) g_ctx[i] = 0.f;
}
__global__ void __launch_bounds__(256) k_ctx()
{
    __shared__ float sk[16][257];
    __shared__ float sv[16][257];
    int bh = blockIdx.x;
    int ch = blockIdx.y;
    int b = bh >> 2, h = bh & 3;
    long rowbase = ((long)b * 64 + h * 16) * 32768 + ch * 256;
    int t = threadIdx.x;
    for (int i = t; i < 16 * 256; i += 256) {
        int d = i >> 8, n = i & 255;
        sk[d][n] = g_ks[rowbase + (long)d * 32768 + n];
        sv[d][n] = g_vs[rowbase + (long)d * 32768 + n];
    }
    __syncthreads();
    int d = t >> 4, e = t & 15;
    float a = 0.f;
#pragma unroll 8
    for (int n = 0; n < 256; n++) a += sk[d][n] * sv[e][n];
    atomicAdd(&g_ctx[(bh << 8) + (d << 4) + e], a);
}

// ==================================================================
// K5: q softmax + ctx^T q + unsqueeze
// ==================================================================
__global__ void __launch_bounds__(128) k_att()
{
    int r = blockIdx.x, b = blockIdx.y;
    __shared__ float cs[NHEAD * DD * DD];
    int t = threadIdx.x;
    for (int i = t; i < NHEAD * DD * DD; i += 128) cs[i] = g_ctx[b * (NHEAD * DD * DD) + i];
    __syncthreads();
    int cp = t;
    float qv[64];
    const float* qbase = g_qs + (long)b * 64 * 32768 + r * 128 + cp;
#pragma unroll
    for (int c = 0; c < 64; c++) qv[c] = qbase[(long)c * 32768];
    int odd = r & 1;
    float2* out = (float2*)(g_att + ((long)b * 64) * 65536 + (long)r * 256) + cp;
#pragma unroll
    for (int h = 0; h < 4; h++) {
        float m = -1e30f;
#pragma unroll
        for (int d = 0; d < 16; d++) m = fmaxf(m, qv[h * 16 + d]);
        float s = 0.f;
#pragma unroll
        for (int d = 0; d < 16; d++) { float e = __expf(qv[h * 16 + d] - m); qv[h * 16 + d] = e; s += e; }
        float inv = 1.0f / s;
#pragma unroll
        for (int e = 0; e < 16; e++) {
            float a = 0.f;
#pragma unroll
            for (int d = 0; d < 16; d++) a += cs[h * 256 + d * 16 + e] * qv[h * 16 + d];
            a *= inv;
            int c = h * 16 + e;
            float2 v = odd ? make_float2(0.f, a) : make_float2(a, 0.f);
            out[(long)c * 32768] = v;
        }
    }
}

// ==================================================================
// K6: conv5x5 (64->128) packed f32x2.
// block 256: os = t&3 -> 2 oc; g = t>>2: py = g>>3 (8 rows), pairs at lx = 2*(g&7)+16*pp
// tile: 8 rows x 64 cols, 8 oc. grid (4, 32, B*16)
// ==================================================================
__global__ void __launch_bounds__(256, 2) k_conv5x5(
    const float* __restrict__ rb, float* __restrict__ out)
{
    __shared__ __align__(16) ull s_in2[12 * 68];
    __shared__ __align__(16) ull s_w2[8 * 30];
    int t = threadIdx.x;
    int bz = blockIdx.z;
    int b = bz >> 4, ocb = (bz & 15) * 8;
    int y0 = blockIdx.y * 8, x0 = blockIdx.x * 64;
    int os = t & 3, g = t >> 2;
    int py = g >> 3;
    int gx = (g & 7) * 2;                 // pair base; pairs at gx + 16*pp
    int o0 = ocb + 2 * os;

    ull acc0[4], acc1[4];
    float bv0 = rb[o0], bv1 = rb[o0 + 1];
#pragma unroll
    for (int pp = 0; pp < 4; pp++) { acc0[pp] = pk2(bv0, bv0); acc1[pp] = pk2(bv1, bv1); }

    const float* inb = g_att + (long)b * 64 * 65536;

    for (int ic = 0; ic < 64; ic++) {
        // stage input pairs (12 x 68 entries, halo included)
        for (int i = t; i < 816; i += 256) {
            int iy = i / 68, ix = i - iy * 68;
            int gy = y0 - 2 + iy, gxx = x0 - 2 + ix;
            const float* p = inb + (long)ic * 65536 + gy * 256 + gxx;
            bool yok = (gy >= 0 && gy < 256);
            float v0 = (yok && gxx >= 0 && gxx < 256) ? p[0] : 0.f;
            float v1 = (yok && gxx + 1 >= 0 && gxx + 1 < 256) ? p[1] : 0.f;
            s_in2[i] = pk2(v0, v1);
        }
        // stage duplicated-pair weights for 8 oc
        for (int i = t; i < 240; i += 256)
            s_w2[i] = g_rw2[((long)ic * 128 + ocb) * 30 + i];
        __syncthreads();

        const ull* w0 = s_w2 + (2 * os) * 30;
        const ull* w1 = w0 + 30;
#pragma unroll
        for (int ky = 0; ky < 5; ky++) {
            ulonglong2 waA = *(const ulonglong2*)(w0 + ky * 6);
            ulonglong2 waB = *(const ulonglong2*)(w0 + ky * 6 + 2);
            ull wa4 = w0[ky * 6 + 4];
            ulonglong2 wbA = *(const ulonglong2*)(w1 + ky * 6);
            ulonglong2 wbB = *(const ulonglong2*)(w1 + ky * 6 + 2);
            ull wb4 = w1[ky * 6 + 4];
            const ull* rowp = s_in2 + (py + ky) * 68;
#pragma unroll
            for (int pp = 0; pp < 4; pp++) {
                int xx = gx + 16 * pp;
                ulonglong2 mA = *(const ulonglong2*)(rowp + xx);
                ulonglong2 mB = *(const ulonglong2*)(rowp + xx + 2);
                ull m4 = rowp[xx + 4];
                fma2(acc0[pp], waA.x, mA.x); fma2(acc1[pp], wbA.x, mA.x);
                fma2(acc0[pp], waA.y, mA.y); fma2(acc1[pp], wbA.y, mA.y);
                fma2(acc0[pp], waB.x, mB.x); fma2(acc1[pp], wbB.x, mB.x);
                fma2(acc0[pp], waB.y, mB.y); fma2(acc1[pp], wbB.y, mB.y);
                fma2(acc0[pp], wa4, m4);     fma2(acc1[pp], wb4, m4);
            }
        }
        __syncthreads();
    }

    int gy = y0 + py;
    long base0 = ((long)b * 128 + o0) * 65536 + (long)gy * 256 + x0;
#pragma unroll
    for (int pp = 0; pp < 4; pp++) {
        int gxp = gx + 16 * pp;
        float lo, hi;
        upk2(lo, hi, acc0[pp]);
        *(float2*)(out + base0 + gxp) = make_float2(lo, hi);
        upk2(lo, hi, acc1[pp]);
        *(float2*)(out + base0 + 65536 + gxp) = make_float2(lo, hi);
    }
}

// ==================================================================
// K7: m1 = gelu(conv1x1 128->256) packed. block 128: thread -> oc {2t, 2t+1}, 16 pixel-pairs
// ==================================================================
__global__ void __launch_bounds__(128) k_m1(
    const float* __restrict__ att, const float* __restrict__ bias)
{
    __shared__ __align__(16) float sbuf[8448];   // phase A x[128][32]; phase B out[256][33]
    __shared__ __align__(16) float s_wT[2048];   // 8 ic x 256 oc
    int t = threadIdx.x;
    long pix0 = (long)blockIdx.x * 32;
    int b = (int)(pix0 >> 16);
    int pp0 = (int)(pix0 & 65535);
    const float* ab = att + ((long)b * 128) * 65536 + pp0;
#pragma unroll 4
    for (int i = t; i < 4096; i += 128) {
        int ic = i >> 5, p = i & 31;
        sbuf[i] = ab[(long)ic * 65536 + p];
    }
    int oc0 = 2 * t;
    float b0 = bias[oc0], b1 = bias[oc0 + 1];
    ull acc0[16], acc1[16];
#pragma unroll
    for (int j = 0; j < 16; j++) { acc0[j] = pk2(b0, b0); acc1[j] = pk2(b1, b1); }

    for (int c8 = 0; c8 < 128; c8 += 8) {
        __syncthreads();
        for (int i = t; i < 512; i += 128)
            *(float4*)(s_wT + i * 4) = *(const float4*)(g_w1T + c8 * 256 + i * 4);
        __syncthreads();
#pragma unroll
        for (int k = 0; k < 8; k++) {
            ull wp = *(const ull*)(s_wT + k * 256 + oc0);
            float f0, f1; upk2(f0, f1, wp);
            ull w2a = pk2(f0, f0), w2b = pk2(f1, f1);
            const ulonglong2* xr = (const ulonglong2*)(sbuf + (c8 + k) * 32);
#pragma unroll
            for (int j = 0; j < 8; j++) {
                ulonglong2 x2 = xr[j];
                fma2(acc0[2 * j],     w2a, x2.x); fma2(acc0[2 * j + 1], w2a, x2.y);
                fma2(acc1[2 * j],     w2b, x2.x); fma2(acc1[2 * j + 1], w2b, x2.y);
            }
        }
    }
    __syncthreads();
#pragma unroll
    for (int j = 0; j < 16; j++) {
        float lo, hi;
        upk2(lo, hi, acc0[j]);
        sbuf[oc0 * 33 + 2 * j]     = gelu_f(lo);
        sbuf[oc0 * 33 + 2 * j + 1] = gelu_f(hi);
        upk2(lo, hi, acc1[j]);
        sbuf[(oc0 + 1) * 33 + 2 * j]     = gelu_f(lo);
        sbuf[(oc0 + 1) * 33 + 2 * j + 1] = gelu_f(hi);
    }
    __syncthreads();
    float* ob = g_m1 + ((long)b * 256) * 65536 + pp0;
#pragma unroll 4
    for (int i = t; i < 8192; i += 128) {
        int o = i >> 5, p = i & 31;
        ob[(long)o * 65536 + p] = sbuf[o * 33 + p];
    }
}

// ==================================================================
// K8: m2 = gelu(depthwise 3x3, 256 ch)
// ==================================================================
__global__ void __launch_bounds__(256) k_m2(
    const float* __restrict__ w, const float* __restrict__ bias)
{
    int r = blockIdx.x;
    int bc = blockIdx.y;
    int c = bc & 255;
    const float* base = g_m1 + (long)bc * 65536;
    __shared__ float srow[3][258];
    for (int i = threadIdx.x; i < 3 * 258; i += 256) {
        int row = i / 258, xx = i % 258;
        int yy = r - 1 + row, x = xx - 1;
        srow[row][xx] = (yy >= 0 && yy < 256 && x >= 0 && x < 256) ? base[yy * 256 + x] : 0.f;
    }
    __syncthreads();
    float wl[9];
#pragma unroll
    for (int i = 0; i < 9; i++) wl[i] = w[c * 9 + i];
    int x = threadIdx.x;
    float acc = bias[c];
#pragma unroll
    for (int ky = 0; ky < 3; ky++)
#pragma unroll
        for (int kx = 0; kx < 3; kx++)
            acc += srow[ky][x + kx] * wl[ky * 3 + kx];
    g_m2[(long)bc * 65536 + (long)r * 256 + x] = gelu_f(acc);
}

// ==================================================================
// K9: out += conv1x1(m2, 256->128) packed. block 64: thread -> oc {2t,2t+1}, 16 pairs
// ==================================================================
__global__ void __launch_bounds__(64) k_m3(
    float* __restrict__ out, const float* __restrict__ bias)
{
    __shared__ __align__(16) float sbuf[8448];   // phase A x[256][32]; phase B out[128][33]
    __shared__ __align__(16) float s_wT[1024];   // 8 ic x 128 oc
    int t = threadIdx.x;
    long pix0 = (long)blockIdx.x * 32;
    int b = (int)(pix0 >> 16);
    int pp0 = (int)(pix0 & 65535);
    const float* ib = g_m2 + ((long)b * 256) * 65536 + pp0;
#pragma unroll 8
    for (int i = t; i < 8192; i += 64) {
        int ic = i >> 5, p = i & 31;
        sbuf[i] = ib[(long)ic * 65536 + p];
    }
    int oc0 = 2 * t;
    float b0 = bias[oc0], b1 = bias[oc0 + 1];
    ull acc0[16], acc1[16];
#pragma unroll
    for (int j = 0; j < 16; j++) { acc0[j] = pk2(b0, b0); acc1[j] = pk2(b1, b1); }

    for (int c8 = 0; c8 < 256; c8 += 8) {
        __syncthreads();
        for (int i = t; i < 256; i += 64)
            *(float4*)(s_wT + i * 4) = *(const float4*)(g_w3T + c8 * 128 + i * 4);
        __syncthreads();
#pragma unroll
        for (int k = 0; k < 8; k++) {
            ull wp = *(const ull*)(s_wT + k * 128 + oc0);
            float f0, f1; upk2(f0, f1, wp);
            ull w2a = pk2(f0, f0), w2b = pk2(f1, f1);
            const ulonglong2* xr = (const ulonglong2*)(sbuf + (c8 + k) * 32);
#pragma unroll
            for (int j = 0; j < 8; j++) {
                ulonglong2 x2 = xr[j];
                fma2(acc0[2 * j],     w2a, x2.x); fma2(acc0[2 * j + 1], w2a, x2.y);
                fma2(acc1[2 * j],     w2b, x2.x); fma2(acc1[2 * j + 1], w2b, x2.y);
            }
        }
    }
    __syncthreads();
#pragma unroll
    for (int j = 0; j < 16; j++) {
        float lo, hi;
        upk2(lo, hi, acc0[j]);
        sbuf[oc0 * 33 + 2 * j]     = lo;
        sbuf[oc0 * 33 + 2 * j + 1] = hi;
        upk2(lo, hi, acc1[j]);
        sbuf[(oc0 + 1) * 33 + 2 * j]     = lo;
        sbuf[(oc0 + 1) * 33 + 2 * j + 1] = hi;
    }
    __syncthreads();
    float* ob = out + ((long)b * 128) * 65536 + pp0;
#pragma unroll 8
    for (int i = t; i < 4096; i += 64) {
        int o = i >> 5, p = i & 31;
        long a = (long)o * 65536 + p;
        ob[a] = ob[a] + sbuf[o * 33 + p];
    }
}

// ==================================================================
extern "C" void kernel_launch(void* const* d_in, const int* in_sizes, int n_in,
                              void* d_out, int out_size)
{
    const float* x1  = (const float*)d_in[0];
    const float* x2  = (const float*)d_in[1];
    const float* q1w = (const float*)d_in[2];  const float* q1b = (const float*)d_in[3];
    const float* q2w = (const float*)d_in[4];  const float* q2b = (const float*)d_in[5];
    const float* k1w = (const float*)d_in[6];  const float* k1b = (const float*)d_in[7];
    const float* k2w = (const float*)d_in[8];  const float* k2b = (const float*)d_in[9];
    const float* v1w = (const float*)d_in[10]; const float* v1b = (const float*)d_in[11];
    const float* v2w = (const float*)d_in[12]; const float* v2b = (const float*)d_in[13];
    const float* rw  = (const float*)d_in[14]; const float* rb  = (const float*)d_in[15];
    const float* m1w = (const float*)d_in[16]; const float* m1b = (const float*)d_in[17];
    const float* m2w = (const float*)d_in[18]; const float* m2b = (const float*)d_in[19];
    const float* m3w = (const float*)d_in[20]; const float* m3b = (const float*)d_in[21];
    float* out = (float*)d_out;

    k_prep<<<800, 256>>>(m1w, m3w, rw);
    k_qkv1x1<<<4096, 256>>>(x1, x2, q1w, q1b, k1w, k1b, v1w, v1b);
    k_dw_squeeze<<<dim3(256, 256, 3), 128>>>(q2w, q2b, k2w, k2b, v2w, v2b);
    k_ksoftmax<<<256, 256>>>();
    k_zero_ctx<<<16, 256>>>();
    k_ctx<<<dim3(16, 128), 256>>>();
    k_att<<<dim3(256, 4), 128>>>();
    k_conv5x5<<<dim3(4, 32, 64), 256>>>(rb, out);
    k_m1<<<8192, 128>>>(out, m1b);
    k_m2<<<dim3(256, 1024), 256>>>(m2w, m2b);
    k_m3<<<8192, 64>>>(out, m3b);
}

// round 3
// speedup vs baseline: 1.2084x; 1.0494x over previous
#include <cuda_runtime.h>
#include <math.h>

typedef unsigned long long ull;

// ---------------- problem constants ----------------
#define BB    4
#define CC    64
#define HH    256
#define WW    256
#define NPIX  65536
#define NSQ   32768
#define NHEAD 4
#define DD    16

// ---------------- scratch ----------------
__device__ float g_tq[BB * CC * NPIX];
__device__ float g_tk[BB * CC * NPIX];
__device__ float g_tv[BB * CC * NPIX];
__device__ float g_qs[BB * CC * NSQ];
__device__ float g_ks[BB * CC * NSQ];
__device__ float g_vs[BB * CC * NSQ];
__device__ float g_ctx[BB * NHEAD * DD * DD];
__device__ float g_att[BB * CC * NPIX];
__device__ float g_m1[BB * 4 * CC * NPIX];
__device__ float g_m2[BB * 4 * CC * NPIX];
__device__ __align__(16) float g_w1T[128 * 256];
__device__ __align__(16) float g_w3T[256 * 128];
__device__ __align__(16) ull   g_rw2[64 * 128 * 30];   // [ic][oc][30] duplicated pairs

// ---------------- f32x2 helpers ----------------
__device__ __forceinline__ ull pk2(float lo, float hi) {
    ull r; asm("mov.b64 %0,{%1,%2};" : "=l"(r) : "f"(lo), "f"(hi)); return r;
}
__device__ __forceinline__ void upk2(float& lo, float& hi, ull v) {
    asm("mov.b64 {%0,%1},%2;" : "=f"(lo), "=f"(hi) : "l"(v));
}
__device__ __forceinline__ void fma2(ull& d, ull a, ull b) {
    asm("fma.rn.f32x2 %0,%1,%2,%0;" : "+l"(d) : "l"(a), "l"(b));
}
__device__ __forceinline__ float gelu_f(float x) {
    return 0.5f * x * (1.0f + erff(x * 0.7071067811865476f));
}

// ==================================================================
// K0: prepack
// ==================================================================
__global__ void __launch_bounds__(256) k_prep(
    const float* __restrict__ m1w, const float* __restrict__ m3w, const float* __restrict__ rw)
{
    int i = blockIdx.x * 256 + threadIdx.x;
    if (i < 32768) {
        { int oc = i >> 7, ic = i & 127; g_w1T[ic * 256 + oc] = m1w[i]; }
        { int oc = i >> 8, ic = i & 255; g_w3T[ic * 128 + oc] = m3w[i]; }
    }
    if (i < 204800) {
        int k = i % 25; int rest = i / 25;
        int ic = rest & 63, oc = rest >> 6;
        int ky = k / 5, kx = k - ky * 5;
        float v = rw[i];
        g_rw2[((long)ic * 128 + oc) * 30 + ky * 6 + kx] = pk2(v, v);
    }
}

// ==================================================================
// K1: fused 1x1 convs q/k/v
// ==================================================================
__device__ __forceinline__ void loadwT(float* ws, const float* __restrict__ w) {
    for (int i = threadIdx.x; i < 4096; i += 256) {
        int oc = i >> 6, ic = i & 63;
        ws[ic * 68 + oc] = w[i];
    }
}
__device__ __forceinline__ void mm16(const float* __restrict__ ws, const float xr[64],
                                     int chunk, float acc[16]) {
#pragma unroll
    for (int o = 0; o < 16; o++) acc[o] = 0.f;
#pragma unroll
    for (int ic = 0; ic < 64; ic++) {
        float xv = xr[ic];
        const float4* w4 = reinterpret_cast<const float4*>(ws + ic * 68 + chunk * 16);
#pragma unroll
        for (int j = 0; j < 4; j++) {
            float4 w = w4[j];
            acc[j * 4 + 0] += w.x * xv;
            acc[j * 4 + 1] += w.y * xv;
            acc[j * 4 + 2] += w.z * xv;
            acc[j * 4 + 3] += w.w * xv;
        }
    }
}
__global__ void __launch_bounds__(256) k_qkv1x1(
    const float* __restrict__ x1, const float* __restrict__ x2,
    const float* __restrict__ wq, const float* __restrict__ bq,
    const float* __restrict__ wk, const float* __restrict__ bk,
    const float* __restrict__ wv, const float* __restrict__ bv)
{
    __shared__ float ws[64 * 68];
    int t = threadIdx.x;
    int px = t & 63, chunk = t >> 6;
    long base = (long)blockIdx.x * 64;
    int b = (int)(base >> 16);
    int pix = (int)(base & 65535) + px;
    int y = pix >> 8, xc = pix & 255;
    int par = (y + xc) & 1;

    float xr[64];
    const float* xb = x1 + ((long)b * 64) * 65536 + pix;
#pragma unroll
    for (int ic = 0; ic < 64; ic++) xr[ic] = xb[(long)ic * 65536];

    float acc[16];
    loadwT(ws, wq); __syncthreads();
    mm16(ws, xr, chunk, acc);
#pragma unroll
    for (int o = 0; o < 16; o++) {
        int oc = chunk * 16 + o; float bias = bq[oc];
        g_tq[((long)b * 64 + oc) * 65536 + pix] = (par == 0) ? acc[o] + bias : bias;
    }
    __syncthreads();
    loadwT(ws, wk); __syncthreads();
    mm16(ws, xr, chunk, acc);
#pragma unroll
    for (int o = 0; o < 16; o++) {
        int oc = chunk * 16 + o; float bias = bk[oc];
        g_tk[((long)b * 64 + oc) * 65536 + pix] = (par == 1) ? acc[o] + bias : bias;
    }
    __syncthreads();
    loadwT(ws, wv); __syncthreads();
    const float* xb2 = x2 + ((long)b * 64) * 65536 + pix;
#pragma unroll
    for (int ic = 0; ic < 64; ic++) xr[ic] = xb2[(long)ic * 65536];
    mm16(ws, xr, chunk, acc);
#pragma unroll
    for (int o = 0; o < 16; o++) {
        int oc = chunk * 16 + o;
        g_tv[((long)b * 64 + oc) * 65536 + pix] = acc[o] + bv[oc];
    }
}

// ==================================================================
// K2: depthwise 3x3 + parity squeeze, 8 rows per block
// grid (H/8, B*C, 3), block 128
// ==================================================================
__global__ void __launch_bounds__(128) k_dw_squeeze(
    const float* __restrict__ q2w, const float* __restrict__ q2b,
    const float* __restrict__ k2w, const float* __restrict__ k2b,
    const float* __restrict__ v2w, const float* __restrict__ v2b)
{
    int r0 = blockIdx.x * 8;
    int bc = blockIdx.y;
    int c = bc & 63;
    int which = blockIdx.z;
    const float* src; const float* wz; const float* bz; float* dst; int pbase;
    if (which == 0)      { src = g_tq; wz = q2w; bz = q2b; dst = g_qs; pbase = 0; } // joff=r&1
    else if (which == 1) { src = g_tk; wz = k2w; bz = k2b; dst = g_ks; pbase = 1; } // joff=1-(r&1)
    else                 { src = g_tv; wz = v2w; bz = v2b; dst = g_vs; pbase = 1; }

    __shared__ float srow[10][258];
    const float* base = src + (long)bc * 65536;
    for (int i = threadIdx.x; i < 10 * 258; i += 128) {
        int row = i / 258, xx = i % 258;
        int yy = r0 - 1 + row, x = xx - 1;
        srow[row][xx] = (yy >= 0 && yy < 256 && x >= 0 && x < 256) ? base[yy * 256 + x] : 0.f;
    }
    __syncthreads();
    float w[9];
#pragma unroll
    for (int i = 0; i < 9; i++) w[i] = wz[c * 9 + i];
    float bias = bz[c];
    int cp = threadIdx.x;
#pragma unroll
    for (int rr = 0; rr < 8; rr++) {
        int r = r0 + rr;
        int joff = pbase ? (1 - (r & 1)) : (r & 1);
        int j = 2 * cp + joff;
        float acc = bias;
#pragma unroll
        for (int ky = 0; ky < 3; ky++)
#pragma unroll
            for (int kx = 0; kx < 3; kx++)
                acc += srow[rr + ky][j + kx] * w[ky * 3 + kx];
        dst[(long)bc * 32768 + r * 128 + cp] = acc;
    }
}

// ==================================================================
// K3: k softmax
// ==================================================================
__global__ void __launch_bounds__(256) k_ksoftmax()
{
    int bc = blockIdx.x;
    float* row = g_ks + (long)bc * 32768;
    __shared__ float red[256];
    int t = threadIdx.x;
    float m = -1e30f;
    for (int i = t; i < 32768; i += 256) m = fmaxf(m, row[i]);
    red[t] = m; __syncthreads();
    for (int s = 128; s > 0; s >>= 1) { if (t < s) red[t] = fmaxf(red[t], red[t + s]); __syncthreads(); }
    m = red[0]; __syncthreads();
    float sum = 0.f;
    for (int i = t; i < 32768; i += 256) sum += __expf(row[i] - m);
    red[t] = sum; __syncthreads();
    for (int s = 128; s > 0; s >>= 1) { if (t < s) red[t] += red[t + s]; __syncthreads(); }
    float inv = 1.0f / red[0];
    for (int i = t; i < 32768; i += 256) row[i] = __expf(row[i] - m) * inv;
}

// ==================================================================
// K4: ctx
// ==================================================================
__global__ void __launch_bounds__(256) k_zero_ctx()
{
    int i = blockIdx.x * 256 + threadIdx.x;
    if (i < BB * NHEAD * DD * DD) g_ctx[i] = 0.f;
}
__global__ void __launch_bounds__(256) k_ctx()
{
    __shared__ float sk[16][257];
    __shared__ float sv[16][257];
    int bh = blockIdx.x;
    int ch = blockIdx.y;
    int b = bh >> 2, h = bh & 3;
    long rowbase = ((long)b * 64 + h * 16) * 32768 + ch * 256;
    int t = threadIdx.x;
    for (int i = t; i < 16 * 256; i += 256) {
        int d = i >> 8, n = i & 255;
        sk[d][n] = g_ks[rowbase + (long)d * 32768 + n];
        sv[d][n] = g_vs[rowbase + (long)d * 32768 + n];
    }
    __syncthreads();
    int d = t >> 4, e = t & 15;
    float a = 0.f;
#pragma unroll 8
    for (int n = 0; n < 256; n++) a += sk[d][n] * sv[e][n];
    atomicAdd(&g_ctx[(bh << 8) + (d << 4) + e], a);
}

// ==================================================================
// K5: q softmax + ctx^T q + unsqueeze
// ==================================================================
__global__ void __launch_bounds__(128) k_att()
{
    int r = blockIdx.x, b = blockIdx.y;
    __shared__ float cs[NHEAD * DD * DD];
    int t = threadIdx.x;
    for (int i = t; i < NHEAD * DD * DD; i += 128) cs[i] = g_ctx[b * (NHEAD * DD * DD) + i];
    __syncthreads();
    int cp = t;
    float qv[64];
    const float* qbase = g_qs + (long)b * 64 * 32768 + r * 128 + cp;
#pragma unroll
    for (int c = 0; c < 64; c++) qv[c] = qbase[(long)c * 32768];
    int odd = r & 1;
    float2* out = (float2*)(g_att + ((long)b * 64) * 65536 + (long)r * 256) + cp;
#pragma unroll
    for (int h = 0; h < 4; h++) {
        float m = -1e30f;
#pragma unroll
        for (int d = 0; d < 16; d++) m = fmaxf(m, qv[h * 16 + d]);
        float s = 0.f;
#pragma unroll
        for (int d = 0; d < 16; d++) { float e = __expf(qv[h * 16 + d] - m); qv[h * 16 + d] = e; s += e; }
        float inv = 1.0f / s;
#pragma unroll
        for (int e = 0; e < 16; e++) {
            float a = 0.f;
#pragma unroll
            for (int d = 0; d < 16; d++) a += cs[h * 256 + d * 16 + e] * qv[h * 16 + d];
            a *= inv;
            int c = h * 16 + e;
            float2 v = odd ? make_float2(0.f, a) : make_float2(a, 0.f);
            out[(long)c * 32768] = v;
        }
    }
}

// ==================================================================
// K6: conv5x5 (64->128), f32x2, 16 oc/block, tile 8x32, double-buffered.
// block 256: os=t&7 -> 2 oc; g=t>>3: py=g>>2, gxp=(g&3)*2; pairs at gxp+8*pp
// grid (W/32=8, H/8=32, B*8=32)
// ==================================================================
#define C5_INW 36      // floats per staged row (x0-2 .. x0+33)
#define C5_INE 35      // pair entries per row
#define C5_NIN (12*C5_INE)   // 420
#define C5_NW  480           // 16 oc * 30

__global__ void __launch_bounds__(256, 3) k_conv5x5(
    const float* __restrict__ rb, float* __restrict__ out)
{
    __shared__ __align__(16) ull s_in2[2][12 * C5_INW];
    __shared__ __align__(16) ull s_w2[2][C5_NW];
    int t = threadIdx.x;
    int bz = blockIdx.z;
    int b = bz >> 3, ocb = (bz & 7) * 16;
    int y0 = blockIdx.y * 8, x0 = blockIdx.x * 32;
    int os = t & 7, g = t >> 3;
    int py = g >> 2;
    int gxp = (g & 3) * 2;
    int o0 = ocb + 2 * os;

    // ---- precompute ic-invariant staging addresses ----
    // entry A: i = t (< 420 always); entry B: i = t + 256 (if < 420)
    int iyA = t / C5_INE, ixA = t - iyA * C5_INE;
    int gyA = y0 - 2 + iyA, gxA = x0 - 2 + ixA;
    bool yokA = (gyA >= 0 && gyA < 256);
    bool a0ok = yokA && (gxA >= 0) && (gxA < 256);
    bool a1ok = yokA && (gxA + 1 >= 0) && (gxA + 1 < 256);
    int offA = gyA * 256 + gxA;
    int iB = t + 256;
    bool hasB = iB < C5_NIN;
    int iyB = iB / C5_INE, ixB = iB - iyB * C5_INE;
    int gyB = y0 - 2 + iyB, gxB = x0 - 2 + ixB;
    bool yokB = (gyB >= 0 && gyB < 256);
    bool b0ok = hasB && yokB && (gxB >= 0) && (gxB < 256);
    bool b1ok = hasB && yokB && (gxB + 1 >= 0) && (gxB + 1 < 256);
    int offB = gyB * 256 + gxB;
    int sA = iyA * C5_INW + ixA;
    int sB = iyB * C5_INW + ixB;
    bool hasW2 = (t + 256) < C5_NW;
    long wbase = (long)ocb * 30 + t;   // + ic*128*30 per ic

    const float* inb = g_att + (long)b * 64 * 65536;
    float bv0 = rb[o0], bv1 = rb[o0 + 1];
    ull acc0[4], acc1[4];
#pragma unroll
    for (int pp = 0; pp < 4; pp++) { acc0[pp] = pk2(bv0, bv0); acc1[pp] = pk2(bv1, bv1); }

    // ---- prologue: stage ic=0 into buf 0 ----
    {
        const float* p = inb + offA;
        float va0 = a0ok ? p[0] : 0.f;
        float va1 = a1ok ? p[1] : 0.f;
        s_in2[0][sA] = pk2(va0, va1);
        if (hasB) {
            const float* q = inb + offB;
            float vb0 = b0ok ? q[0] : 0.f;
            float vb1 = b1ok ? q[1] : 0.f;
            s_in2[0][sB] = pk2(vb0, vb1);
        }
        s_w2[0][t] = g_rw2[wbase];
        if (hasW2) s_w2[0][t + 256] = g_rw2[wbase + 256];
    }
    __syncthreads();

    for (int ic = 0; ic < 64; ic++) {
        int cur = ic & 1;
        // ---- issue next-ic loads into registers (no STS yet) ----
        float va0 = 0.f, va1 = 0.f, vb0 = 0.f, vb1 = 0.f;
        ull w0v = 0, w1v = 0;
        if (ic < 63) {
            const float* p = inb + (long)(ic + 1) * 65536 + offA;
            va0 = a0ok ? p[0] : 0.f;
            va1 = a1ok ? p[1] : 0.f;
            if (hasB) {
                const float* q = inb + (long)(ic + 1) * 65536 + offB;
                vb0 = b0ok ? q[0] : 0.f;
                vb1 = b1ok ? q[1] : 0.f;
            }
            long wb = (long)(ic + 1) * (128 * 30) + wbase;
            w0v = g_rw2[wb];
            if (hasW2) w1v = g_rw2[wb + 256];
        }

        // ---- compute from current buffer ----
        const ull* w0 = s_w2[cur] + (2 * os) * 30;
        const ull* w1 = w0 + 30;
#pragma unroll
        for (int ky = 0; ky < 5; ky++) {
            ulonglong2 waA = *(const ulonglong2*)(w0 + ky * 6);
            ulonglong2 waB = *(const ulonglong2*)(w0 + ky * 6 + 2);
            ull wa4 = w0[ky * 6 + 4];
            ulonglong2 wbA = *(const ulonglong2*)(w1 + ky * 6);
            ulonglong2 wbB = *(const ulonglong2*)(w1 + ky * 6 + 2);
            ull wb4 = w1[ky * 6 + 4];
            const ull* rowp = s_in2[cur] + (py + ky) * C5_INW;
#pragma unroll
            for (int pp = 0; pp < 4; pp++) {
                int xx = gxp + 8 * pp;
                ulonglong2 mA = *(const ulonglong2*)(rowp + xx);
                ulonglong2 mB = *(const ulonglong2*)(rowp + xx + 2);
                ull m4 = rowp[xx + 4];
                fma2(acc0[pp], waA.x, mA.x); fma2(acc1[pp], wbA.x, mA.x);
                fma2(acc0[pp], waA.y, mA.y); fma2(acc1[pp], wbA.y, mA.y);
                fma2(acc0[pp], waB.x, mB.x); fma2(acc1[pp], wbB.x, mB.x);
                fma2(acc0[pp], waB.y, mB.y); fma2(acc1[pp], wbB.y, mB.y);
                fma2(acc0[pp], wa4, m4);     fma2(acc1[pp], wb4, m4);
            }
        }

        // ---- store staged data to the other buffer ----
        if (ic < 63) {
            int nxt = cur ^ 1;
            s_in2[nxt][sA] = pk2(va0, va1);
            if (hasB) s_in2[nxt][sB] = pk2(vb0, vb1);
            s_w2[nxt][t] = w0v;
            if (hasW2) s_w2[nxt][t + 256] = w1v;
        }
        __syncthreads();
    }

    int gy = y0 + py;
    long base0 = ((long)b * 128 + o0) * 65536 + (long)gy * 256 + x0;
#pragma unroll
    for (int pp = 0; pp < 4; pp++) {
        int xx = gxp + 8 * pp;
        float lo, hi;
        upk2(lo, hi, acc0[pp]);
        *(float2*)(out + base0 + xx) = make_float2(lo, hi);
        upk2(lo, hi, acc1[pp]);
        *(float2*)(out + base0 + 65536 + xx) = make_float2(lo, hi);
    }
}

// ==================================================================
// K7: m1 = gelu(conv1x1 128->256) packed
// ==================================================================
__global__ void __launch_bounds__(128) k_m1(
    const float* __restrict__ att, const float* __restrict__ bias)
{
    __shared__ __align__(16) float sbuf[8448];
    __shared__ __align__(16) float s_wT[2048];
    int t = threadIdx.x;
    long pix0 = (long)blockIdx.x * 32;
    int b = (int)(pix0 >> 16);
    int pp0 = (int)(pix0 & 65535);
    const float* ab = att + ((long)b * 128) * 65536 + pp0;
#pragma unroll 4
    for (int i = t; i < 4096; i += 128) {
        int ic = i >> 5, p = i & 31;
        sbuf[i] = ab[(long)ic * 65536 + p];
    }
    int oc0 = 2 * t;
    float b0 = bias[oc0], b1 = bias[oc0 + 1];
    ull acc0[16], acc1[16];
#pragma unroll
    for (int j = 0; j < 16; j++) { acc0[j] = pk2(b0, b0); acc1[j] = pk2(b1, b1); }

    for (int c8 = 0; c8 < 128; c8 += 8) {
        __syncthreads();
        for (int i = t; i < 512; i += 128)
            *(float4*)(s_wT + i * 4) = *(const float4*)(g_w1T + c8 * 256 + i * 4);
        __syncthreads();
#pragma unroll
        for (int k = 0; k < 8; k++) {
            ull wp = *(const ull*)(s_wT + k * 256 + oc0);
            float f0, f1; upk2(f0, f1, wp);
            ull w2a = pk2(f0, f0), w2b = pk2(f1, f1);
            const ulonglong2* xr = (const ulonglong2*)(sbuf + (c8 + k) * 32);
#pragma unroll
            for (int j = 0; j < 8; j++) {
                ulonglong2 x2 = xr[j];
                fma2(acc0[2 * j],     w2a, x2.x); fma2(acc0[2 * j + 1], w2a, x2.y);
                fma2(acc1[2 * j],     w2b, x2.x); fma2(acc1[2 * j + 1], w2b, x2.y);
            }
        }
    }
    __syncthreads();
#pragma unroll
    for (int j = 0; j < 16; j++) {
        float lo, hi;
        upk2(lo, hi, acc0[j]);
        sbuf[oc0 * 33 + 2 * j]     = gelu_f(lo);
        sbuf[oc0 * 33 + 2 * j + 1] = gelu_f(hi);
        upk2(lo, hi, acc1[j]);
        sbuf[(oc0 + 1) * 33 + 2 * j]     = gelu_f(lo);
        sbuf[(oc0 + 1) * 33 + 2 * j + 1] = gelu_f(hi);
    }
    __syncthreads();
    float* ob = g_m1 + ((long)b * 256) * 65536 + pp0;
#pragma unroll 4
    for (int i = t; i < 8192; i += 128) {
        int o = i >> 5, p = i & 31;
        ob[(long)o * 65536 + p] = sbuf[o * 33 + p];
    }
}

// ==================================================================
// K8: m2 = gelu(depthwise 3x3, 256 ch), 8 rows per block
// grid (H/8, B*256), block 256
// ==================================================================
__global__ void __launch_bounds__(256) k_m2(
    const float* __restrict__ w, const float* __restrict__ bias)
{
    int r0 = blockIdx.x * 8;
    int bc = blockIdx.y;
    int c = bc & 255;
    const float* base = g_m1 + (long)bc * 65536;
    __shared__ float srow[10][258];
    for (int i = threadIdx.x; i < 10 * 258; i += 256) {
        int row = i / 258, xx = i % 258;
        int yy = r0 - 1 + row, x = xx - 1;
        srow[row][xx] = (yy >= 0 && yy < 256 && x >= 0 && x < 256) ? base[yy * 256 + x] : 0.f;
    }
    __syncthreads();
    float wl[9];
#pragma unroll
    for (int i = 0; i < 9; i++) wl[i] = w[c * 9 + i];
    float bv = bias[c];
    int x = threadIdx.x;
#pragma unroll
    for (int rr = 0; rr < 8; rr++) {
        float acc = bv;
#pragma unroll
        for (int ky = 0; ky < 3; ky++)
#pragma unroll
            for (int kx = 0; kx < 3; kx++)
                acc += srow[rr + ky][x + kx] * wl[ky * 3 + kx];
        g_m2[(long)bc * 65536 + (long)(r0 + rr) * 256 + x] = gelu_f(acc);
    }
}

// ==================================================================
// K9: out += conv1x1(m2, 256->128) packed
// ==================================================================
__global__ void __launch_bounds__(64) k_m3(
    float* __restrict__ out, const float* __restrict__ bias)
{
    __shared__ __align__(16) float sbuf[8448];
    __shared__ __align__(16) float s_wT[1024];
    int t = threadIdx.x;
    long pix0 = (long)blockIdx.x * 32;
    int b = (int)(pix0 >> 16);
    int pp0 = (int)(pix0 & 65535);
    const float* ib = g_m2 + ((long)b * 256) * 65536 + pp0;
#pragma unroll 8
    for (int i = t; i < 8192; i += 64) {
        int ic = i >> 5, p = i & 31;
        sbuf[i] = ib[(long)ic * 65536 + p];
    }
    int oc0 = 2 * t;
    float b0 = bias[oc0], b1 = bias[oc0 + 1];
    ull acc0[16], acc1[16];
#pragma unroll
    for (int j = 0; j < 16; j++) { acc0[j] = pk2(b0, b0); acc1[j] = pk2(b1, b1); }

    for (int c8 = 0; c8 < 256; c8 += 8) {
        __syncthreads();
        for (int i = t; i < 256; i += 64)
            *(float4*)(s_wT + i * 4) = *(const float4*)(g_w3T + c8 * 128 + i * 4);
        __syncthreads();
#pragma unroll
        for (int k = 0; k < 8; k++) {
            ull wp = *(const ull*)(s_wT + k * 128 + oc0);
            float f0, f1; upk2(f0, f1, wp);
            ull w2a = pk2(f0, f0), w2b = pk2(f1, f1);
            const ulonglong2* xr = (const ulonglong2*)(sbuf + (c8 + k) * 32);
#pragma unroll
            for (int j = 0; j < 8; j++) {
                ulonglong2 x2 = xr[j];
                fma2(acc0[2 * j],     w2a, x2.x); fma2(acc0[2 * j + 1], w2a, x2.y);
                fma2(acc1[2 * j],     w2b, x2.x); fma2(acc1[2 * j + 1], w2b, x2.y);
            }
        }
    }
    __syncthreads();
#pragma unroll
    for (int j = 0; j < 16; j++) {
        float lo, hi;
        upk2(lo, hi, acc0[j]);
        sbuf[oc0 * 33 + 2 * j]     = lo;
        sbuf[oc0 * 33 + 2 * j + 1] = hi;
        upk2(lo, hi, acc1[j]);
        sbuf[(oc0 + 1) * 33 + 2 * j]     = lo;
        sbuf[(oc0 + 1) * 33 + 2 * j + 1] = hi;
    }
    __syncthreads();
    float* ob = out + ((long)b * 128) * 65536 + pp0;
#pragma unroll 8
    for (int i = t; i < 4096; i += 64) {
        int o = i >> 5, p = i & 31;
        long a = (long)o * 65536 + p;
        ob[a] = ob[a] + sbuf[o * 33 + p];
    }
}

// ==================================================================
extern "C" void kernel_launch(void* const* d_in, const int* in_sizes, int n_in,
                              void* d_out, int out_size)
{
    const float* x1  = (const float*)d_in[0];
    const float* x2  = (const float*)d_in[1];
    const float* q1w = (const float*)d_in[2];  const float* q1b = (const float*)d_in[3];
    const float* q2w = (const float*)d_in[4];  const float* q2b = (const float*)d_in[5];
    const float* k1w = (const float*)d_in[6];  const float* k1b = (const float*)d_in[7];
    const float* k2w = (const float*)d_in[8];  const float* k2b = (const float*)d_in[9];
    const float* v1w = (const float*)d_in[10]; const float* v1b = (const float*)d_in[11];
    const float* v2w = (const float*)d_in[12]; const float* v2b = (const float*)d_in[13];
    const float* rw  = (const float*)d_in[14]; const float* rb  = (const float*)d_in[15];
    const float* m1w = (const float*)d_in[16]; const float* m1b = (const float*)d_in[17];
    const float* m2w = (const float*)d_in[18]; const float* m2b = (const float*)d_in[19];
    const float* m3w = (const float*)d_in[20]; const float* m3b = (const float*)d_in[21];
    float* out = (float*)d_out;

    k_prep<<<800, 256>>>(m1w, m3w, rw);
    k_qkv1x1<<<4096, 256>>>(x1, x2, q1w, q1b, k1w, k1b, v1w, v1b);
    k_dw_squeeze<<<dim3(32, 256, 3), 128>>>(q2w, q2b, k2w, k2b, v2w, v2b);
    k_ksoftmax<<<256, 256>>>();
    k_zero_ctx<<<16, 256>>>();
    k_ctx<<<dim3(16, 128), 256>>>();
    k_att<<<dim3(256, 4), 128>>>();
    k_conv5x5<<<dim3(8, 32, 32), 256>>>(rb, out);
    k_m1<<<8192, 128>>>(out, m1b);
    k_m2<<<dim3(32, 1024), 256>>>(m2w, m2b);
    k_m3<<<8192, 64>>>(out, m3b);
}